// round 1
// baseline (speedup 1.0000x reference)
#include <cuda_runtime.h>
#include <cstdint>

// SGIntoKGPool: out[b,m,c] = (sum_n adj[b,n,m] * x[b,c,n]) / max(sum_n adj[b,n,m], 1)
// B=8, C=64, N=4096 (=64*64), M=2048.
// fp32 SIMT GEMM using packed fma.rn.f32x2 (Blackwell FFMA2), fused degree computation.

#define BZv 8
#define Cv  64
#define Nv  4096
#define Mv  2048
#define MT  128      // m-tile per block
#define KS  16       // k-tile
#define NTILES (Nv / KS)
#define XSTRIDE 68   // padded Xs row stride (floats) to reduce STS bank conflicts

typedef unsigned long long ull;

__device__ __forceinline__ ull rep2(float x) {
    ull r; asm("mov.b64 %0, {%1, %1};" : "=l"(r) : "f"(x)); return r;
}
__device__ __forceinline__ void fma2(ull &d, ull a, ull b) {
    asm("fma.rn.f32x2 %0, %1, %2, %0;" : "+l"(d) : "l"(a), "l"(b));
}
__device__ __forceinline__ void add2(ull &d, ull a) {
    asm("add.rn.f32x2 %0, %0, %1;" : "+l"(d) : "l"(a));
}
__device__ __forceinline__ float lo32(ull v) { return __uint_as_float((unsigned)(v & 0xffffffffull)); }
__device__ __forceinline__ float hi32(ull v) { return __uint_as_float((unsigned)(v >> 32)); }

__global__ __launch_bounds__(256, 1)
void sg_kg_pool_kernel(const float* __restrict__ x,    // (B, C, N)
                       const float* __restrict__ adj,  // (B, N, M)
                       float* __restrict__ out)        // (B, M, C)
{
    __shared__ float As[2][KS * MT];        // A tile: [k][m], 8KB each
    __shared__ float Xs[2][KS * XSTRIDE];   // X tile transposed: [k][c], padded
    __shared__ float degS[KS * MT];         // degree partials [ty][m]
    __shared__ float invS[MT];              // 1/max(degree,1)

    const int b   = blockIdx.y;
    const int m0  = blockIdx.x * MT;
    const int tid = threadIdx.x;
    const int tx  = tid & 15;   // m direction (16)
    const int ty  = tid >> 4;   // c direction (16)

    const float* Ab = adj + (size_t)b * Nv * Mv + m0;
    const float* Xb = x   + (size_t)b * Cv * Nv;

    // global-load lane mapping
    const int arow = tid >> 5;         // 0..7 (rows arow and arow+8)
    const int acol = (tid & 31) * 4;   // 0..124
    const int xc   = tid >> 2;         // 0..63
    const int xq   = (tid & 3) * 4;    // 0,4,8,12 (k offset within tile)

    // 16 packed accumulators: acc[p][cc] holds m-pair p, c = ty*4 + cc
    ull acc[4][4];
    #pragma unroll
    for (int p = 0; p < 4; p++)
        #pragma unroll
        for (int cc = 0; cc < 4; cc++) acc[p][cc] = 0ull;
    ull dacc[4] = {0ull, 0ull, 0ull, 0ull};   // packed degree partials for this thread's 8 m's

    // ---- prologue: load tile 0 into smem buffer 0 ----
    float4 pa0 = *(const float4*)(Ab + (size_t)arow       * Mv + acol);
    float4 pa1 = *(const float4*)(Ab + (size_t)(arow + 8) * Mv + acol);
    float4 pxv = *(const float4*)(Xb + (size_t)xc * Nv + xq);

    *(float4*)&As[0][arow * MT + acol]       = pa0;
    *(float4*)&As[0][(arow + 8) * MT + acol] = pa1;
    Xs[0][(xq + 0) * XSTRIDE + xc] = pxv.x;
    Xs[0][(xq + 1) * XSTRIDE + xc] = pxv.y;
    Xs[0][(xq + 2) * XSTRIDE + xc] = pxv.z;
    Xs[0][(xq + 3) * XSTRIDE + xc] = pxv.w;
    __syncthreads();

    int cur = 0;
    for (int t = 0; t < NTILES; t++) {
        // prefetch next tile into registers (overlaps with compute below)
        if (t + 1 < NTILES) {
            const float* An = Ab + (size_t)(t + 1) * KS * Mv;
            pa0 = *(const float4*)(An + (size_t)arow       * Mv + acol);
            pa1 = *(const float4*)(An + (size_t)(arow + 8) * Mv + acol);
            pxv = *(const float4*)(Xb + (size_t)xc * Nv + (t + 1) * KS + xq);
        }

        const float* Ac = As[cur];
        const float* Xc = Xs[cur];

        // fused degree slice: this thread sums adj row k_local = ty of this tile
        {
            ulonglong2 d0 = *(const ulonglong2*)(Ac + ty * MT + tx * 4);
            ulonglong2 d1 = *(const ulonglong2*)(Ac + ty * MT + 64 + tx * 4);
            add2(dacc[0], d0.x); add2(dacc[1], d0.y);
            add2(dacc[2], d1.x); add2(dacc[3], d1.y);
        }

        // main compute: 16 k-steps, 16 packed FFMA2 each
        #pragma unroll
        for (int k = 0; k < KS; k++) {
            ulonglong2 a0 = *(const ulonglong2*)(Ac + k * MT + tx * 4);
            ulonglong2 a1 = *(const ulonglong2*)(Ac + k * MT + 64 + tx * 4);
            float4 xv = *(const float4*)(Xc + k * XSTRIDE + ty * 4);
            ull xx0 = rep2(xv.x), xx1 = rep2(xv.y), xx2 = rep2(xv.z), xx3 = rep2(xv.w);
            ull ap0 = a0.x, ap1 = a0.y, ap2 = a1.x, ap3 = a1.y;
            fma2(acc[0][0], ap0, xx0); fma2(acc[0][1], ap0, xx1);
            fma2(acc[0][2], ap0, xx2); fma2(acc[0][3], ap0, xx3);
            fma2(acc[1][0], ap1, xx0); fma2(acc[1][1], ap1, xx1);
            fma2(acc[1][2], ap1, xx2); fma2(acc[1][3], ap1, xx3);
            fma2(acc[2][0], ap2, xx0); fma2(acc[2][1], ap2, xx1);
            fma2(acc[2][2], ap2, xx2); fma2(acc[2][3], ap2, xx3);
            fma2(acc[3][0], ap3, xx0); fma2(acc[3][1], ap3, xx1);
            fma2(acc[3][2], ap3, xx2); fma2(acc[3][3], ap3, xx3);
        }

        // stage next tile into the other buffer
        if (t + 1 < NTILES) {
            int nxt = cur ^ 1;
            *(float4*)&As[nxt][arow * MT + acol]       = pa0;
            *(float4*)&As[nxt][(arow + 8) * MT + acol] = pa1;
            Xs[nxt][(xq + 0) * XSTRIDE + xc] = pxv.x;
            Xs[nxt][(xq + 1) * XSTRIDE + xc] = pxv.y;
            Xs[nxt][(xq + 2) * XSTRIDE + xc] = pxv.z;
            Xs[nxt][(xq + 3) * XSTRIDE + xc] = pxv.w;
        }
        __syncthreads();
        cur ^= 1;
    }

    // ---- degree reduction across the 16 ty slices ----
    #pragma unroll
    for (int p = 0; p < 4; p++) {
        int mbase = (p < 2) ? (tx * 4 + p * 2) : (64 + tx * 4 + (p - 2) * 2);
        degS[ty * MT + mbase]     = lo32(dacc[p]);
        degS[ty * MT + mbase + 1] = hi32(dacc[p]);
    }
    __syncthreads();
    if (tid < MT) {
        float s = 0.0f;
        #pragma unroll
        for (int r = 0; r < KS; r++) s += degS[r * MT + tid];
        invS[tid] = 1.0f / fmaxf(s, 1.0f);
    }
    __syncthreads();

    // ---- epilogue: scale and store, float4 along c ----
    float* Ob = out + (size_t)b * Mv * Cv + (size_t)m0 * Cv + ty * 4;
    #pragma unroll
    for (int p = 0; p < 4; p++) {
        int mbase = (p < 2) ? (tx * 4 + p * 2) : (64 + tx * 4 + (p - 2) * 2);
        float inv0 = invS[mbase];
        float inv1 = invS[mbase + 1];
        float4 v0, v1;
        v0.x = lo32(acc[p][0]) * inv0; v0.y = lo32(acc[p][1]) * inv0;
        v0.z = lo32(acc[p][2]) * inv0; v0.w = lo32(acc[p][3]) * inv0;
        v1.x = hi32(acc[p][0]) * inv1; v1.y = hi32(acc[p][1]) * inv1;
        v1.z = hi32(acc[p][2]) * inv1; v1.w = hi32(acc[p][3]) * inv1;
        *(float4*)(Ob + (size_t)mbase * Cv)       = v0;
        *(float4*)(Ob + (size_t)(mbase + 1) * Cv) = v1;
    }
}

extern "C" void kernel_launch(void* const* d_in, const int* in_sizes, int n_in,
                              void* d_out, int out_size)
{
    // metadata order: sg_node_feats (8*64*4096 = 2,097,152), sg_kg_adj (8*4096*2048 = 67,108,864)
    const float* x;
    const float* adj;
    if (in_sizes[0] == BZv * Cv * Nv) {
        x   = (const float*)d_in[0];
        adj = (const float*)d_in[1];
    } else {
        x   = (const float*)d_in[1];
        adj = (const float*)d_in[0];
    }
    float* out = (float*)d_out;

    dim3 grid(Mv / MT, BZv);   // 16 x 8 = 128 blocks
    dim3 block(256);
    sg_kg_pool_kernel<<<grid, block>>>(x, adj, out);
}